// round 1
// baseline (speedup 1.0000x reference)
#include <cuda_runtime.h>

#define EMBD   384
#define FFN_D  1536
#define T_SEQ  200
#define NH     6
#define HS     64
#define BATCH  256
#define M_ROWS (BATCH * T_SEQ)   // 51200

// ---------------- scratch (no allocations allowed) ----------------
__device__ float g_H [M_ROWS * EMBD];
__device__ float g_Q [M_ROWS * EMBD];
__device__ float g_K [M_ROWS * EMBD];
__device__ float g_V [M_ROWS * EMBD];
__device__ float g_A [M_ROWS * EMBD];
__device__ float g_X1[M_ROWS * EMBD];
__device__ float g_F [M_ROWS * FFN_D];

// ---------------- LayerNorm (one block per row of 384) ----------------
__global__ void ln_kernel(const float* __restrict__ x,
                          const float* __restrict__ g,
                          const float* __restrict__ be,
                          float* __restrict__ out)
{
    __shared__ float red[4];
    int row = blockIdx.x;
    int t = threadIdx.x;               // 128 threads, 3 elems each
    const float* xr = x + (size_t)row * EMBD;

    float v0 = xr[t], v1 = xr[t + 128], v2 = xr[t + 256];
    float s = v0 + v1 + v2;
    #pragma unroll
    for (int o = 16; o; o >>= 1) s += __shfl_xor_sync(0xffffffffu, s, o);
    if ((t & 31) == 0) red[t >> 5] = s;
    __syncthreads();
    float mean = (red[0] + red[1] + red[2] + red[3]) * (1.0f / EMBD);
    __syncthreads();

    float d0 = v0 - mean, d1 = v1 - mean, d2 = v2 - mean;
    float sq = d0 * d0 + d1 * d1 + d2 * d2;
    #pragma unroll
    for (int o = 16; o; o >>= 1) sq += __shfl_xor_sync(0xffffffffu, sq, o);
    if ((t & 31) == 0) red[t >> 5] = sq;
    __syncthreads();
    float var = (red[0] + red[1] + red[2] + red[3]) * (1.0f / EMBD);
    float inv = rsqrtf(var + 1e-5f);

    float* orow = out + (size_t)row * EMBD;
    orow[t]       = d0 * inv * g[t]       + be[t];
    orow[t + 128] = d1 * inv * g[t + 128] + be[t + 128];
    orow[t + 256] = d2 * inv * g[t + 256] + be[t + 256];
}

// ---------------- Tiled SGEMM: C(M,N) = A(M,K) @ B(K,N) [+epilogue] ----------------
// EPI: 0 = none, 1 = bias + relu, 2 = bias + residual add
// 256 threads, 64x64 tile, BK=16, 4x4 per-thread microtile.
template <int EPI>
__global__ void gemm_kernel(const float* __restrict__ A,
                            const float* __restrict__ Bw,
                            const float* __restrict__ bias,
                            const float* __restrict__ add,
                            float* __restrict__ C,
                            int M, int N, int K)
{
    __shared__ float As[16 * 68];   // transposed A tile, stride 68 (pad: conflicts + 16B align)
    __shared__ float Bs[16 * 64];

    int tid = threadIdx.x;
    int tx = tid & 15, ty = tid >> 4;
    int m0 = blockIdx.y * 64, n0 = blockIdx.x * 64;

    float acc[4][4] = {};

    // A tile load: thread -> (row am, 4 consecutive k at ak)
    int am = tid >> 2, ak = (tid & 3) * 4;
    // B tile load: thread -> (k-row bk, 4 consecutive n at bn)
    int bk = tid >> 4, bn = (tid & 15) * 4;

    const float* Ag = A + (size_t)(m0 + am) * K + ak;
    const float* Bg = Bw + (size_t)bk * N + n0 + bn;

    for (int k0 = 0; k0 < K; k0 += 16) {
        float4 a4 = *(const float4*)(Ag + k0);
        float4 b4 = *(const float4*)(Bg + (size_t)k0 * N);
        *(float4*)&Bs[bk * 64 + bn] = b4;
        As[(ak + 0) * 68 + am] = a4.x;
        As[(ak + 1) * 68 + am] = a4.y;
        As[(ak + 2) * 68 + am] = a4.z;
        As[(ak + 3) * 68 + am] = a4.w;
        __syncthreads();

        #pragma unroll
        for (int k = 0; k < 16; k++) {
            float4 av = *(const float4*)&As[k * 68 + ty * 4];
            float4 bv = *(const float4*)&Bs[k * 64 + tx * 4];
            float a[4] = {av.x, av.y, av.z, av.w};
            float b[4] = {bv.x, bv.y, bv.z, bv.w};
            #pragma unroll
            for (int i = 0; i < 4; i++)
                #pragma unroll
                for (int j = 0; j < 4; j++)
                    acc[i][j] += a[i] * b[j];
        }
        __syncthreads();
    }

    float bx[4];
    if (EPI != 0) {
        #pragma unroll
        for (int j = 0; j < 4; j++) bx[j] = bias[n0 + tx * 4 + j];
    }
    #pragma unroll
    for (int i = 0; i < 4; i++) {
        int r = m0 + ty * 4 + i;
        size_t off = (size_t)r * N + n0 + tx * 4;
        float v[4];
        #pragma unroll
        for (int j = 0; j < 4; j++) v[j] = acc[i][j];
        if (EPI == 1) {
            #pragma unroll
            for (int j = 0; j < 4; j++) v[j] = fmaxf(v[j] + bx[j], 0.0f);
        } else if (EPI == 2) {
            float4 r4 = *(const float4*)(add + off);
            v[0] += bx[0] + r4.x; v[1] += bx[1] + r4.y;
            v[2] += bx[2] + r4.z; v[3] += bx[3] + r4.w;
        }
        float4 o4 = {v[0], v[1], v[2], v[3]};
        *(float4*)(C + off) = o4;
    }
}

// ---------------- Attention: one block per (batch, head) ----------------
// SMEM: K (pad 65), V (stride 64), per-warp scores + q row.
#define ATTN_SMEM ((T_SEQ * 65 + T_SEQ * 64 + 8 * T_SEQ + 8 * HS) * 4)

__global__ void attn_kernel(const float* __restrict__ Q,
                            const float* __restrict__ K,
                            const float* __restrict__ V,
                            float* __restrict__ O)
{
    extern __shared__ float sm[];
    float* Ks  = sm;                       // T_SEQ * 65
    float* Vs  = Ks + T_SEQ * 65;          // T_SEQ * 64
    float* Ssc = Vs + T_SEQ * 64;          // 8 * T_SEQ
    float* Qs  = Ssc + 8 * T_SEQ;          // 8 * HS

    int bh = blockIdx.x;
    int b = bh / NH, h = bh % NH;
    int tid = threadIdx.x;

    const float* Kg = K + (size_t)(b * T_SEQ) * EMBD + h * HS;
    const float* Vg = V + (size_t)(b * T_SEQ) * EMBD + h * HS;
    for (int i = tid; i < T_SEQ * HS; i += blockDim.x) {
        int j = i >> 6, d = i & 63;
        Ks[j * 65 + d] = Kg[(size_t)j * EMBD + d];
        Vs[j * 64 + d] = Vg[(size_t)j * EMBD + d];
    }
    __syncthreads();

    int warp = tid >> 5, lane = tid & 31;
    float* myS = Ssc + warp * T_SEQ;
    float* myQ = Qs + warp * HS;
    const float scale = 0.05103103630798288f;   // 384^-0.5

    for (int t = warp; t < T_SEQ; t += 8) {
        const float* qrow = Q + (size_t)(b * T_SEQ + t) * EMBD + h * HS;
        myQ[lane]      = qrow[lane];
        myQ[lane + 32] = qrow[lane + 32];
        __syncwarp();

        for (int j = lane; j <= t; j += 32) {
            float s = 0.f;
            #pragma unroll
            for (int d = 0; d < HS; d++) s += myQ[d] * Ks[j * 65 + d];
            myS[j] = s * scale;
        }
        __syncwarp();

        float m = -1e30f;
        for (int j = lane; j <= t; j += 32) m = fmaxf(m, myS[j]);
        #pragma unroll
        for (int o = 16; o; o >>= 1) m = fmaxf(m, __shfl_xor_sync(0xffffffffu, m, o));

        float sum = 0.f;
        for (int j = lane; j <= t; j += 32) {
            float p = __expf(myS[j] - m);
            myS[j] = p;
            sum += p;
        }
        #pragma unroll
        for (int o = 16; o; o >>= 1) sum += __shfl_xor_sync(0xffffffffu, sum, o);
        __syncwarp();
        float inv = 1.f / sum;

        float a0 = 0.f, a1 = 0.f;
        for (int j = 0; j <= t; j++) {
            float p = myS[j];
            a0 += p * Vs[j * 64 + lane];
            a1 += p * Vs[j * 64 + lane + 32];
        }
        float* orow = O + (size_t)(b * T_SEQ + t) * EMBD + h * HS;
        orow[lane]      = a0 * inv;
        orow[lane + 32] = a1 * inv;
        __syncwarp();
    }
}

// ---------------- launch ----------------
extern "C" void kernel_launch(void* const* d_in, const int* in_sizes, int n_in,
                              void* d_out, int out_size)
{
    const float* x     = (const float*)d_in[0];
    const float* Wq    = (const float*)d_in[1];
    const float* Wk    = (const float*)d_in[2];
    const float* Wv    = (const float*)d_in[3];
    const float* Wproj = (const float*)d_in[4];
    const float* bproj = (const float*)d_in[5];
    const float* W1    = (const float*)d_in[6];
    const float* b1    = (const float*)d_in[7];
    const float* W2    = (const float*)d_in[8];
    const float* b2    = (const float*)d_in[9];
    const float* g1    = (const float*)d_in[10];
    const float* be1   = (const float*)d_in[11];
    const float* g2    = (const float*)d_in[12];
    const float* be2   = (const float*)d_in[13];

    float *H, *Q, *K, *V, *A, *X1, *F;
    cudaGetSymbolAddress((void**)&H,  g_H);
    cudaGetSymbolAddress((void**)&Q,  g_Q);
    cudaGetSymbolAddress((void**)&K,  g_K);
    cudaGetSymbolAddress((void**)&V,  g_V);
    cudaGetSymbolAddress((void**)&A,  g_A);
    cudaGetSymbolAddress((void**)&X1, g_X1);
    cudaGetSymbolAddress((void**)&F,  g_F);

    cudaFuncSetAttribute(attn_kernel,
                         cudaFuncAttributeMaxDynamicSharedMemorySize, ATTN_SMEM);

    dim3 blk(256);
    dim3 g384(EMBD / 64, M_ROWS / 64);
    dim3 gffn(FFN_D / 64, M_ROWS / 64);

    // 1) h = LN(x)
    ln_kernel<<<M_ROWS, 128>>>(x, g1, be1, H);
    // 2) q,k,v = h @ W{q,k,v}
    gemm_kernel<0><<<g384, blk>>>(H, Wq, nullptr, nullptr, Q, M_ROWS, EMBD, EMBD);
    gemm_kernel<0><<<g384, blk>>>(H, Wk, nullptr, nullptr, K, M_ROWS, EMBD, EMBD);
    gemm_kernel<0><<<g384, blk>>>(H, Wv, nullptr, nullptr, V, M_ROWS, EMBD, EMBD);
    // 3) att = softmax(causal(q k^T * scale)) v
    attn_kernel<<<BATCH * NH, blk, ATTN_SMEM>>>(Q, K, V, A);
    // 4) x1 = x + att @ Wproj + bproj
    gemm_kernel<2><<<g384, blk>>>(A, Wproj, bproj, x, X1, M_ROWS, EMBD, EMBD);
    // 5) h2 = LN(x1)
    ln_kernel<<<M_ROWS, 128>>>(X1, g2, be2, H);
    // 6) f = relu(h2 @ W1 + b1)
    gemm_kernel<1><<<gffn, blk>>>(H, W1, b1, nullptr, F, M_ROWS, FFN_D, EMBD);
    // 7) out = x1 + f @ W2 + b2
    gemm_kernel<2><<<g384, blk>>>(F, W2, b2, X1, (float*)d_out, M_ROWS, EMBD, FFN_D);
}

// round 2
// speedup vs baseline: 1.0027x; 1.0027x over previous
#include <cuda_runtime.h>

#define EMBD   384
#define FFN_D  1536
#define T_SEQ  200
#define NH     6
#define HS     64
#define BATCH  256
#define M_ROWS (BATCH * T_SEQ)   // 51200

// ---------------- scratch (no allocations allowed) ----------------
__device__ float g_H [M_ROWS * EMBD];
__device__ float g_Q [M_ROWS * EMBD];
__device__ float g_K [M_ROWS * EMBD];
__device__ float g_V [M_ROWS * EMBD];
__device__ float g_A [M_ROWS * EMBD];
__device__ float g_X1[M_ROWS * EMBD];
__device__ float g_F [M_ROWS * FFN_D];

// ---------------- LayerNorm (one block per row of 384) ----------------
__global__ void ln_kernel(const float* __restrict__ x,
                          const float* __restrict__ g,
                          const float* __restrict__ be,
                          float* __restrict__ out)
{
    __shared__ float red[4];
    int row = blockIdx.x;
    int t = threadIdx.x;               // 128 threads, 3 elems each
    const float* xr = x + (size_t)row * EMBD;

    float v0 = xr[t], v1 = xr[t + 128], v2 = xr[t + 256];
    float s = v0 + v1 + v2;
    #pragma unroll
    for (int o = 16; o; o >>= 1) s += __shfl_xor_sync(0xffffffffu, s, o);
    if ((t & 31) == 0) red[t >> 5] = s;
    __syncthreads();
    float mean = (red[0] + red[1] + red[2] + red[3]) * (1.0f / EMBD);
    __syncthreads();

    float d0 = v0 - mean, d1 = v1 - mean, d2 = v2 - mean;
    float sq = d0 * d0 + d1 * d1 + d2 * d2;
    #pragma unroll
    for (int o = 16; o; o >>= 1) sq += __shfl_xor_sync(0xffffffffu, sq, o);
    if ((t & 31) == 0) red[t >> 5] = sq;
    __syncthreads();
    float var = (red[0] + red[1] + red[2] + red[3]) * (1.0f / EMBD);
    float inv = rsqrtf(var + 1e-5f);

    float* orow = out + (size_t)row * EMBD;
    orow[t]       = d0 * inv * g[t]       + be[t];
    orow[t + 128] = d1 * inv * g[t + 128] + be[t + 128];
    orow[t + 256] = d2 * inv * g[t + 256] + be[t + 256];
}

// ---------------- Tiled SGEMM: C(M,N) = A(M,K) @ B(K,N) [+epilogue] ----------------
// EPI: 0 = none, 1 = bias + relu, 2 = bias + residual add
// 256 threads, 64x64 tile, BK=16, 4x4 per-thread microtile.
template <int EPI>
__global__ void gemm_kernel(const float* __restrict__ A,
                            const float* __restrict__ Bw,
                            const float* __restrict__ bias,
                            const float* __restrict__ add,
                            float* __restrict__ C,
                            int M, int N, int K)
{
    __shared__ float As[16 * 68];   // transposed A tile, stride 68 (pad: conflicts + 16B align)
    __shared__ float Bs[16 * 64];

    int tid = threadIdx.x;
    int tx = tid & 15, ty = tid >> 4;
    int m0 = blockIdx.y * 64, n0 = blockIdx.x * 64;

    float acc[4][4] = {};

    // A tile load: thread -> (row am, 4 consecutive k at ak)
    int am = tid >> 2, ak = (tid & 3) * 4;
    // B tile load: thread -> (k-row bk, 4 consecutive n at bn)
    int bk = tid >> 4, bn = (tid & 15) * 4;

    const float* Ag = A + (size_t)(m0 + am) * K + ak;
    const float* Bg = Bw + (size_t)bk * N + n0 + bn;

    for (int k0 = 0; k0 < K; k0 += 16) {
        float4 a4 = *(const float4*)(Ag + k0);
        float4 b4 = *(const float4*)(Bg + (size_t)k0 * N);
        *(float4*)&Bs[bk * 64 + bn] = b4;
        As[(ak + 0) * 68 + am] = a4.x;
        As[(ak + 1) * 68 + am] = a4.y;
        As[(ak + 2) * 68 + am] = a4.z;
        As[(ak + 3) * 68 + am] = a4.w;
        __syncthreads();

        #pragma unroll
        for (int k = 0; k < 16; k++) {
            float4 av = *(const float4*)&As[k * 68 + ty * 4];
            float4 bv = *(const float4*)&Bs[k * 64 + tx * 4];
            float a[4] = {av.x, av.y, av.z, av.w};
            float b[4] = {bv.x, bv.y, bv.z, bv.w};
            #pragma unroll
            for (int i = 0; i < 4; i++)
                #pragma unroll
                for (int j = 0; j < 4; j++)
                    acc[i][j] += a[i] * b[j];
        }
        __syncthreads();
    }

    float bx[4];
    if (EPI != 0) {
        #pragma unroll
        for (int j = 0; j < 4; j++) bx[j] = bias[n0 + tx * 4 + j];
    }
    #pragma unroll
    for (int i = 0; i < 4; i++) {
        int r = m0 + ty * 4 + i;
        size_t off = (size_t)r * N + n0 + tx * 4;
        float v[4];
        #pragma unroll
        for (int j = 0; j < 4; j++) v[j] = acc[i][j];
        if (EPI == 1) {
            #pragma unroll
            for (int j = 0; j < 4; j++) v[j] = fmaxf(v[j] + bx[j], 0.0f);
        } else if (EPI == 2) {
            float4 r4 = *(const float4*)(add + off);
            v[0] += bx[0] + r4.x; v[1] += bx[1] + r4.y;
            v[2] += bx[2] + r4.z; v[3] += bx[3] + r4.w;
        }
        float4 o4 = {v[0], v[1], v[2], v[3]};
        *(float4*)(C + off) = o4;
    }
}

// ---------------- Attention: one block per (batch, head) ----------------
// SMEM: K (pad 65), V (stride 64), per-warp scores + q row.
#define ATTN_SMEM ((T_SEQ * 65 + T_SEQ * 64 + 8 * T_SEQ + 8 * HS) * 4)

__global__ void attn_kernel(const float* __restrict__ Q,
                            const float* __restrict__ K,
                            const float* __restrict__ V,
                            float* __restrict__ O)
{
    extern __shared__ float sm[];
    float* Ks  = sm;                       // T_SEQ * 65
    float* Vs  = Ks + T_SEQ * 65;          // T_SEQ * 64
    float* Ssc = Vs + T_SEQ * 64;          // 8 * T_SEQ
    float* Qs  = Ssc + 8 * T_SEQ;          // 8 * HS

    int bh = blockIdx.x;
    int b = bh / NH, h = bh % NH;
    int tid = threadIdx.x;

    const float* Kg = K + (size_t)(b * T_SEQ) * EMBD + h * HS;
    const float* Vg = V + (size_t)(b * T_SEQ) * EMBD + h * HS;
    for (int i = tid; i < T_SEQ * HS; i += blockDim.x) {
        int j = i >> 6, d = i & 63;
        Ks[j * 65 + d] = Kg[(size_t)j * EMBD + d];
        Vs[j * 64 + d] = Vg[(size_t)j * EMBD + d];
    }
    __syncthreads();

    int warp = tid >> 5, lane = tid & 31;
    float* myS = Ssc + warp * T_SEQ;
    float* myQ = Qs + warp * HS;
    const float scale = 0.05103103630798288f;   // 384^-0.5

    for (int t = warp; t < T_SEQ; t += 8) {
        const float* qrow = Q + (size_t)(b * T_SEQ + t) * EMBD + h * HS;
        myQ[lane]      = qrow[lane];
        myQ[lane + 32] = qrow[lane + 32];
        __syncwarp();

        for (int j = lane; j <= t; j += 32) {
            float s = 0.f;
            #pragma unroll
            for (int d = 0; d < HS; d++) s += myQ[d] * Ks[j * 65 + d];
            myS[j] = s * scale;
        }
        __syncwarp();

        float m = -1e30f;
        for (int j = lane; j <= t; j += 32) m = fmaxf(m, myS[j]);
        #pragma unroll
        for (int o = 16; o; o >>= 1) m = fmaxf(m, __shfl_xor_sync(0xffffffffu, m, o));

        float sum = 0.f;
        for (int j = lane; j <= t; j += 32) {
            float p = __expf(myS[j] - m);
            myS[j] = p;
            sum += p;
        }
        #pragma unroll
        for (int o = 16; o; o >>= 1) sum += __shfl_xor_sync(0xffffffffu, sum, o);
        __syncwarp();
        float inv = 1.f / sum;

        float a0 = 0.f, a1 = 0.f;
        for (int j = 0; j <= t; j++) {
            float p = myS[j];
            a0 += p * Vs[j * 64 + lane];
            a1 += p * Vs[j * 64 + lane + 32];
        }
        float* orow = O + (size_t)(b * T_SEQ + t) * EMBD + h * HS;
        orow[lane]      = a0 * inv;
        orow[lane + 32] = a1 * inv;
        __syncwarp();
    }
}

// ---------------- launch ----------------
extern "C" void kernel_launch(void* const* d_in, const int* in_sizes, int n_in,
                              void* d_out, int out_size)
{
    const float* x     = (const float*)d_in[0];
    const float* Wq    = (const float*)d_in[1];
    const float* Wk    = (const float*)d_in[2];
    const float* Wv    = (const float*)d_in[3];
    const float* Wproj = (const float*)d_in[4];
    const float* bproj = (const float*)d_in[5];
    const float* W1    = (const float*)d_in[6];
    const float* b1    = (const float*)d_in[7];
    const float* W2    = (const float*)d_in[8];
    const float* b2    = (const float*)d_in[9];
    const float* g1    = (const float*)d_in[10];
    const float* be1   = (const float*)d_in[11];
    const float* g2    = (const float*)d_in[12];
    const float* be2   = (const float*)d_in[13];

    float *H, *Q, *K, *V, *A, *X1, *F;
    cudaGetSymbolAddress((void**)&H,  g_H);
    cudaGetSymbolAddress((void**)&Q,  g_Q);
    cudaGetSymbolAddress((void**)&K,  g_K);
    cudaGetSymbolAddress((void**)&V,  g_V);
    cudaGetSymbolAddress((void**)&A,  g_A);
    cudaGetSymbolAddress((void**)&X1, g_X1);
    cudaGetSymbolAddress((void**)&F,  g_F);

    cudaFuncSetAttribute(attn_kernel,
                         cudaFuncAttributeMaxDynamicSharedMemorySize, ATTN_SMEM);

    dim3 blk(256);
    dim3 g384(EMBD / 64, M_ROWS / 64);
    dim3 gffn(FFN_D / 64, M_ROWS / 64);

    // 1) h = LN(x)
    ln_kernel<<<M_ROWS, 128>>>(x, g1, be1, H);
    // 2) q,k,v = h @ W{q,k,v}
    gemm_kernel<0><<<g384, blk>>>(H, Wq, nullptr, nullptr, Q, M_ROWS, EMBD, EMBD);
    gemm_kernel<0><<<g384, blk>>>(H, Wk, nullptr, nullptr, K, M_ROWS, EMBD, EMBD);
    gemm_kernel<0><<<g384, blk>>>(H, Wv, nullptr, nullptr, V, M_ROWS, EMBD, EMBD);
    // 3) att = softmax(causal(q k^T * scale)) v
    attn_kernel<<<BATCH * NH, blk, ATTN_SMEM>>>(Q, K, V, A);
    // 4) x1 = x + att @ Wproj + bproj
    gemm_kernel<2><<<g384, blk>>>(A, Wproj, bproj, x, X1, M_ROWS, EMBD, EMBD);
    // 5) h2 = LN(x1)
    ln_kernel<<<M_ROWS, 128>>>(X1, g2, be2, H);
    // 6) f = relu(h2 @ W1 + b1)
    gemm_kernel<1><<<gffn, blk>>>(H, W1, b1, nullptr, F, M_ROWS, FFN_D, EMBD);
    // 7) out = x1 + f @ W2 + b2
    gemm_kernel<2><<<g384, blk>>>(F, W2, b2, X1, (float*)d_out, M_ROWS, EMBD, FFN_D);
}

// round 3
// speedup vs baseline: 1.0029x; 1.0002x over previous
#include <cuda_runtime.h>

#define EMBD   384
#define FFN_D  1536
#define T_SEQ  200
#define NH     6
#define HS     64
#define BATCH  256
#define M_ROWS (BATCH * T_SEQ)   // 51200

// ---------------- scratch (no allocations allowed) ----------------
__device__ float g_H [M_ROWS * EMBD];
__device__ float g_Q [M_ROWS * EMBD];
__device__ float g_K [M_ROWS * EMBD];
__device__ float g_V [M_ROWS * EMBD];
__device__ float g_A [M_ROWS * EMBD];
__device__ float g_X1[M_ROWS * EMBD];
__device__ float g_F [M_ROWS * FFN_D];

// ---------------- LayerNorm (one block per row of 384) ----------------
__global__ void ln_kernel(const float* __restrict__ x,
                          const float* __restrict__ g,
                          const float* __restrict__ be,
                          float* __restrict__ out)
{
    __shared__ float red[4];
    int row = blockIdx.x;
    int t = threadIdx.x;               // 128 threads, 3 elems each
    const float* xr = x + (size_t)row * EMBD;

    float v0 = xr[t], v1 = xr[t + 128], v2 = xr[t + 256];
    float s = v0 + v1 + v2;
    #pragma unroll
    for (int o = 16; o; o >>= 1) s += __shfl_xor_sync(0xffffffffu, s, o);
    if ((t & 31) == 0) red[t >> 5] = s;
    __syncthreads();
    float mean = (red[0] + red[1] + red[2] + red[3]) * (1.0f / EMBD);
    __syncthreads();

    float d0 = v0 - mean, d1 = v1 - mean, d2 = v2 - mean;
    float sq = d0 * d0 + d1 * d1 + d2 * d2;
    #pragma unroll
    for (int o = 16; o; o >>= 1) sq += __shfl_xor_sync(0xffffffffu, sq, o);
    if ((t & 31) == 0) red[t >> 5] = sq;
    __syncthreads();
    float var = (red[0] + red[1] + red[2] + red[3]) * (1.0f / EMBD);
    float inv = rsqrtf(var + 1e-5f);

    float* orow = out + (size_t)row * EMBD;
    orow[t]       = d0 * inv * g[t]       + be[t];
    orow[t + 128] = d1 * inv * g[t + 128] + be[t + 128];
    orow[t + 256] = d2 * inv * g[t + 256] + be[t + 256];
}

// ---------------- Tiled SGEMM: C(M,N) = A(M,K) @ B(K,N) [+epilogue] ----------------
// EPI: 0 = none, 1 = bias + relu, 2 = bias + residual add
// 256 threads, 64x64 tile, BK=16, 4x4 per-thread microtile.
template <int EPI>
__global__ void gemm_kernel(const float* __restrict__ A,
                            const float* __restrict__ Bw,
                            const float* __restrict__ bias,
                            const float* __restrict__ add,
                            float* __restrict__ C,
                            int M, int N, int K)
{
    __shared__ float As[16 * 68];   // transposed A tile, stride 68 (pad: conflicts + 16B align)
    __shared__ float Bs[16 * 64];

    int tid = threadIdx.x;
    int tx = tid & 15, ty = tid >> 4;
    int m0 = blockIdx.y * 64, n0 = blockIdx.x * 64;

    float acc[4][4] = {};

    // A tile load: thread -> (row am, 4 consecutive k at ak)
    int am = tid >> 2, ak = (tid & 3) * 4;
    // B tile load: thread -> (k-row bk, 4 consecutive n at bn)
    int bk = tid >> 4, bn = (tid & 15) * 4;

    const float* Ag = A + (size_t)(m0 + am) * K + ak;
    const float* Bg = Bw + (size_t)bk * N + n0 + bn;

    for (int k0 = 0; k0 < K; k0 += 16) {
        float4 a4 = *(const float4*)(Ag + k0);
        float4 b4 = *(const float4*)(Bg + (size_t)k0 * N);
        *(float4*)&Bs[bk * 64 + bn] = b4;
        As[(ak + 0) * 68 + am] = a4.x;
        As[(ak + 1) * 68 + am] = a4.y;
        As[(ak + 2) * 68 + am] = a4.z;
        As[(ak + 3) * 68 + am] = a4.w;
        __syncthreads();

        #pragma unroll
        for (int k = 0; k < 16; k++) {
            float4 av = *(const float4*)&As[k * 68 + ty * 4];
            float4 bv = *(const float4*)&Bs[k * 64 + tx * 4];
            float a[4] = {av.x, av.y, av.z, av.w};
            float b[4] = {bv.x, bv.y, bv.z, bv.w};
            #pragma unroll
            for (int i = 0; i < 4; i++)
                #pragma unroll
                for (int j = 0; j < 4; j++)
                    acc[i][j] += a[i] * b[j];
        }
        __syncthreads();
    }

    float bx[4];
    if (EPI != 0) {
        #pragma unroll
        for (int j = 0; j < 4; j++) bx[j] = bias[n0 + tx * 4 + j];
    }
    #pragma unroll
    for (int i = 0; i < 4; i++) {
        int r = m0 + ty * 4 + i;
        size_t off = (size_t)r * N + n0 + tx * 4;
        float v[4];
        #pragma unroll
        for (int j = 0; j < 4; j++) v[j] = acc[i][j];
        if (EPI == 1) {
            #pragma unroll
            for (int j = 0; j < 4; j++) v[j] = fmaxf(v[j] + bx[j], 0.0f);
        } else if (EPI == 2) {
            float4 r4 = *(const float4*)(add + off);
            v[0] += bx[0] + r4.x; v[1] += bx[1] + r4.y;
            v[2] += bx[2] + r4.z; v[3] += bx[3] + r4.w;
        }
        float4 o4 = {v[0], v[1], v[2], v[3]};
        *(float4*)(C + off) = o4;
    }
}

// ---------------- Attention: one block per (batch, head) ----------------
// SMEM: K (pad 65), V (stride 64), per-warp scores + q row.
#define ATTN_SMEM ((T_SEQ * 65 + T_SEQ * 64 + 8 * T_SEQ + 8 * HS) * 4)

__global__ void attn_kernel(const float* __restrict__ Q,
                            const float* __restrict__ K,
                            const float* __restrict__ V,
                            float* __restrict__ O)
{
    extern __shared__ float sm[];
    float* Ks  = sm;                       // T_SEQ * 65
    float* Vs  = Ks + T_SEQ * 65;          // T_SEQ * 64
    float* Ssc = Vs + T_SEQ * 64;          // 8 * T_SEQ
    float* Qs  = Ssc + 8 * T_SEQ;          // 8 * HS

    int bh = blockIdx.x;
    int b = bh / NH, h = bh % NH;
    int tid = threadIdx.x;

    const float* Kg = K + (size_t)(b * T_SEQ) * EMBD + h * HS;
    const float* Vg = V + (size_t)(b * T_SEQ) * EMBD + h * HS;
    for (int i = tid; i < T_SEQ * HS; i += blockDim.x) {
        int j = i >> 6, d = i & 63;
        Ks[j * 65 + d] = Kg[(size_t)j * EMBD + d];
        Vs[j * 64 + d] = Vg[(size_t)j * EMBD + d];
    }
    __syncthreads();

    int warp = tid >> 5, lane = tid & 31;
    float* myS = Ssc + warp * T_SEQ;
    float* myQ = Qs + warp * HS;
    const float scale = 0.05103103630798288f;   // 384^-0.5

    for (int t = warp; t < T_SEQ; t += 8) {
        const float* qrow = Q + (size_t)(b * T_SEQ + t) * EMBD + h * HS;
        myQ[lane]      = qrow[lane];
        myQ[lane + 32] = qrow[lane + 32];
        __syncwarp();

        for (int j = lane; j <= t; j += 32) {
            float s = 0.f;
            #pragma unroll
            for (int d = 0; d < HS; d++) s += myQ[d] * Ks[j * 65 + d];
            myS[j] = s * scale;
        }
        __syncwarp();

        float m = -1e30f;
        for (int j = lane; j <= t; j += 32) m = fmaxf(m, myS[j]);
        #pragma unroll
        for (int o = 16; o; o >>= 1) m = fmaxf(m, __shfl_xor_sync(0xffffffffu, m, o));

        float sum = 0.f;
        for (int j = lane; j <= t; j += 32) {
            float p = __expf(myS[j] - m);
            myS[j] = p;
            sum += p;
        }
        #pragma unroll
        for (int o = 16; o; o >>= 1) sum += __shfl_xor_sync(0xffffffffu, sum, o);
        __syncwarp();
        float inv = 1.f / sum;

        float a0 = 0.f, a1 = 0.f;
        for (int j = 0; j <= t; j++) {
            float p = myS[j];
            a0 += p * Vs[j * 64 + lane];
            a1 += p * Vs[j * 64 + lane + 32];
        }
        float* orow = O + (size_t)(b * T_SEQ + t) * EMBD + h * HS;
        orow[lane]      = a0 * inv;
        orow[lane + 32] = a1 * inv;
        __syncwarp();
    }
}

// ---------------- launch ----------------
extern "C" void kernel_launch(void* const* d_in, const int* in_sizes, int n_in,
                              void* d_out, int out_size)
{
    const float* x     = (const float*)d_in[0];
    const float* Wq    = (const float*)d_in[1];
    const float* Wk    = (const float*)d_in[2];
    const float* Wv    = (const float*)d_in[3];
    const float* Wproj = (const float*)d_in[4];
    const float* bproj = (const float*)d_in[5];
    const float* W1    = (const float*)d_in[6];
    const float* b1    = (const float*)d_in[7];
    const float* W2    = (const float*)d_in[8];
    const float* b2    = (const float*)d_in[9];
    const float* g1    = (const float*)d_in[10];
    const float* be1   = (const float*)d_in[11];
    const float* g2    = (const float*)d_in[12];
    const float* be2   = (const float*)d_in[13];

    float *H, *Q, *K, *V, *A, *X1, *F;
    cudaGetSymbolAddress((void**)&H,  g_H);
    cudaGetSymbolAddress((void**)&Q,  g_Q);
    cudaGetSymbolAddress((void**)&K,  g_K);
    cudaGetSymbolAddress((void**)&V,  g_V);
    cudaGetSymbolAddress((void**)&A,  g_A);
    cudaGetSymbolAddress((void**)&X1, g_X1);
    cudaGetSymbolAddress((void**)&F,  g_F);

    cudaFuncSetAttribute(attn_kernel,
                         cudaFuncAttributeMaxDynamicSharedMemorySize, ATTN_SMEM);

    dim3 blk(256);
    dim3 g384(EMBD / 64, M_ROWS / 64);
    dim3 gffn(FFN_D / 64, M_ROWS / 64);

    // 1) h = LN(x)
    ln_kernel<<<M_ROWS, 128>>>(x, g1, be1, H);
    // 2) q,k,v = h @ W{q,k,v}
    gemm_kernel<0><<<g384, blk>>>(H, Wq, nullptr, nullptr, Q, M_ROWS, EMBD, EMBD);
    gemm_kernel<0><<<g384, blk>>>(H, Wk, nullptr, nullptr, K, M_ROWS, EMBD, EMBD);
    gemm_kernel<0><<<g384, blk>>>(H, Wv, nullptr, nullptr, V, M_ROWS, EMBD, EMBD);
    // 3) att = softmax(causal(q k^T * scale)) v
    attn_kernel<<<BATCH * NH, blk, ATTN_SMEM>>>(Q, K, V, A);
    // 4) x1 = x + att @ Wproj + bproj
    gemm_kernel<2><<<g384, blk>>>(A, Wproj, bproj, x, X1, M_ROWS, EMBD, EMBD);
    // 5) h2 = LN(x1)
    ln_kernel<<<M_ROWS, 128>>>(X1, g2, be2, H);
    // 6) f = relu(h2 @ W1 + b1)
    gemm_kernel<1><<<gffn, blk>>>(H, W1, b1, nullptr, F, M_ROWS, FFN_D, EMBD);
    // 7) out = x1 + f @ W2 + b2
    gemm_kernel<2><<<g384, blk>>>(F, W2, b2, X1, (float*)d_out, M_ROWS, EMBD, FFN_D);
}